// round 3
// baseline (speedup 1.0000x reference)
#include <cuda_runtime.h>
#include <math.h>

#define BATCH 512
#define NFEAT 128
#define NTRIP 1024
#define KB 8
#define NGRAM 128           // gram blocks (4 antithetic a-values each)
#define NTBLK 4             // triplet blocks
#define NPAIR 8128          // 128*127/2

// ---------------- device scratch (no allocations allowed) --------------------
__device__ float g_m[BATCH * NFEAT];                // m[a][f] row means of D
__device__ float g_g[NFEAT];                        // g[f] grand mean
__device__ float g_part[NGRAM * NFEAT * NFEAT];     // split-K partials of T/2
__device__ float g_S[NFEAT * NFEAT];                // S' (un-normalized Gram)
__device__ float g_tpart[NTBLK];                    // triplet partial sums

// ---- K1: m[a][f] = (1/B) sum_b |x[a][f]-x[b][f]| ---------------------------
__global__ void k_means(const float* __restrict__ emb) {
    int a = blockIdx.x;
    int f = threadIdx.x;
    float xa = emb[a * NFEAT + f];
    float s = 0.f;
#pragma unroll 8
    for (int b = 0; b < BATCH; b++)
        s += fabsf(xa - emb[b * NFEAT + f]);
    g_m[a * NFEAT + f] = s * (1.f / BATCH);
}

// ---- K2: g[f] = mean_a m[a][f] ---------------------------------------------
__global__ void k_g(const float* __restrict__ emb) {
    int f = threadIdx.x;
    float s = 0.f;
#pragma unroll 8
    for (int a = 0; a < BATCH; a++) s += g_m[a * NFEAT + f];
    g_g[f] = s * (1.f / BATCH);
    (void)emb;
}

// ---- K3: T/2 partials: block k sums |dx_i||dx_j| over its (a, b>a) columns --
__global__ void __launch_bounds__(256) k_gram(const float* __restrict__ emb) {
    const int blk = blockIdx.x;
    int alist[4] = {2 * blk, 2 * blk + 1, 510 - 2 * blk, 511 - 2 * blk};

    __shared__ float s_xa[NFEAT];
    __shared__ float s_v[KB][NFEAT];

    const int tid = threadIdx.x;
    const int ty = tid >> 4, tx = tid & 15;
    const int ib = ty * 8, jb = tx * 8;

    float acc[8][8];
#pragma unroll
    for (int u = 0; u < 8; u++)
#pragma unroll
        for (int v = 0; v < 8; v++) acc[u][v] = 0.f;

#pragma unroll 1
    for (int ai = 0; ai < 4; ai++) {
        const int a = alist[ai];
        if (tid < NFEAT) s_xa[tid] = emb[a * NFEAT + tid];
        __syncthreads();

        const int bstart = (a + 1) & ~(KB - 1);
#pragma unroll 1
        for (int b0 = bstart; b0 < BATCH; b0 += KB) {
            // generate KB columns: v[kb][f] = (b>a) ? |xa[f]-xb[f]| : 0
#pragma unroll
            for (int t = 0; t < 4; t++) {
                int e = tid + t * 256;
                int kb = e >> 7, f = e & 127;
                int b = b0 + kb;
                float val = 0.f;
                if (b > a) val = fabsf(s_xa[f] - emb[b * NFEAT + f]);
                s_v[kb][f] = val;
            }
            __syncthreads();

#pragma unroll
            for (int kb = 0; kb < KB; kb++) {
                float4 A0 = *(const float4*)&s_v[kb][ib];
                float4 A1 = *(const float4*)&s_v[kb][ib + 4];
                float4 B0 = *(const float4*)&s_v[kb][jb];
                float4 B1 = *(const float4*)&s_v[kb][jb + 4];
                float av[8] = {A0.x, A0.y, A0.z, A0.w, A1.x, A1.y, A1.z, A1.w};
                float bv[8] = {B0.x, B0.y, B0.z, B0.w, B1.x, B1.y, B1.z, B1.w};
#pragma unroll
                for (int u = 0; u < 8; u++)
#pragma unroll
                    for (int v = 0; v < 8; v++)
                        acc[u][v] += av[u] * bv[v];
            }
            __syncthreads();
        }
    }

    float* out = &g_part[blk * NFEAT * NFEAT];
#pragma unroll
    for (int u = 0; u < 8; u++)
#pragma unroll
        for (int v = 0; v < 8; v++)
            out[(ib + u) * NFEAT + (jb + v)] = acc[u][v];
}

// ---- K4: S'_ij = 2*sum_k part - 2B*sum_a m_ia m_ja + B^2 g_i g_j -----------
__global__ void k_reduce(const float* __restrict__ emb) {
    int idx = blockIdx.x * blockDim.x + threadIdx.x;  // 0..16383
    int i = idx >> 7, j = idx & 127;

    float t = 0.f;
#pragma unroll 8
    for (int k = 0; k < NGRAM; k++) t += g_part[k * NFEAT * NFEAT + idx];

    float mm = 0.f;
#pragma unroll 8
    for (int a = 0; a < BATCH; a++)
        mm += g_m[a * NFEAT + i] * g_m[a * NFEAT + j];

    float B = (float)BATCH;
    g_S[idx] = 2.f * t - 2.f * B * mm + B * B * g_g[i] * g_g[j];
    (void)emb;
}

// ---- K5: triplet loss partials ---------------------------------------------
// Triplet indices: metadata dtype is int32 in practice (JAX x64 disabled), but
// sniff for little-endian int64 (odd 32-bit words all zero) as insurance.
__global__ void k_triplet(const float* __restrict__ emb,
                          const int* __restrict__ trip32) {
    __shared__ float red[256];
    int tid = threadIdx.x;

    // dtype sniff (values are in [0,512), so int64 high words are 0)
    bool is64 = (trip32[1] == 0) && (trip32[3] == 0) &&
                (trip32[5] == 0) && (trip32[7] == 0) &&
                ((trip32[0] | trip32[2] | trip32[4] | trip32[6]) != 0);

    int t = blockIdx.x * 256 + tid;   // 1024 triplets, 4 blocks x 256
    float s = 0.f;
    if (t < NTRIP) {
        int p, q, r;
        if (is64) {
            p = trip32[(3 * t + 0) * 2];
            q = trip32[(3 * t + 1) * 2];
            r = trip32[(3 * t + 2) * 2];
        } else {
            p = trip32[3 * t + 0];
            q = trip32[3 * t + 1];
            r = trip32[3 * t + 2];
        }
        const float* pp = &emb[p * NFEAT];
        const float* pq = &emb[q * NFEAT];
        const float* pr = &emb[r * NFEAT];
        float ap = 0.f, an = 0.f;
#pragma unroll 8
        for (int f = 0; f < NFEAT; f++) {
            float pv = pp[f];
            float d1 = pv - pq[f]; ap += d1 * d1;
            float d2 = pv - pr[f]; an += d2 * d2;
        }
        float l = ap - an + 1.0f;  // MARGIN
        s = (l > 0.f) ? l : 0.f;
    }
    red[tid] = s;
    __syncthreads();
    for (int o = 128; o > 0; o >>= 1) {
        if (tid < o) red[tid] += red[tid + o];
        __syncthreads();
    }
    if (tid == 0) g_tpart[blockIdx.x] = red[0];
}

// ---- K6: epilogue -----------------------------------------------------------
// corr_ij = sqrt(S'_ij) / (S'_ii^(1/4) * S'_jj^(1/4))  (B^2 normalization cancels)
__global__ void k_final(const float* __restrict__ emb, float* __restrict__ out) {
    __shared__ float q[NFEAT];
    __shared__ float red[256];
    int tid = threadIdx.x;
    if (tid < NFEAT) q[tid] = sqrtf(sqrtf(fmaxf(g_S[tid * NFEAT + tid], 0.f)));
    __syncthreads();

    float s = 0.f;
    for (int p = tid; p < NPAIR; p += 256) {
        int off = p, i = 0;
        while (off >= 127 - i) { off -= 127 - i; i++; }
        int j = i + 1 + off;
        float sij = g_S[i * NFEAT + j];
        s += sqrtf(fmaxf(sij, 0.f)) / (q[i] * q[j]);
    }
    red[tid] = s;
    __syncthreads();
    for (int o = 128; o > 0; o >>= 1) {
        if (tid < o) red[tid] += red[tid + o];
        __syncthreads();
    }
    if (tid == 0) {
        float tl = 0.f;
        for (int k = 0; k < NTBLK; k++) tl += g_tpart[k];
        out[0] = tl * (1.f / NTRIP) + red[0] * (1.f / NPAIR);
    }
    (void)emb;
}

// ---- launch -----------------------------------------------------------------
extern "C" void kernel_launch(void* const* d_in, const int* in_sizes, int n_in,
                              void* d_out, int out_size) {
    const float* emb = (const float*)d_in[0];
    const int* trip = (const int*)d_in[1];
    float* out = (float*)d_out;

    k_means<<<BATCH, NFEAT>>>(emb);
    k_g<<<1, NFEAT>>>(emb);
    k_gram<<<NGRAM, 256>>>(emb);
    k_reduce<<<(NFEAT * NFEAT) / 256, 256>>>(emb);
    k_triplet<<<NTBLK, 256>>>(emb, trip);
    k_final<<<1, 256>>>(emb, out);
}